// round 9
// baseline (speedup 1.0000x reference)
#include <cuda_runtime.h>
#include <cuda_bf16.h>
#include <cstdint>

#define DIM 1024
#define NGROUPS 32
#define GSIZE 32
#define TT 1024
#define BB 16
#define MROWS (TT * BB)          // 16384
#define BD (BB * DIM)            // 16384

// ---------------- scratch (device globals; no allocation allowed) ----------------
__device__ float g_vx[MROWS * DIM];
__device__ float g_alpha[MROWS * DIM];
__device__ float g_delta[MROWS * DIM];
__device__ float g_compete[MROWS * DIM];
__device__ float g_xc[MROWS * DIM];          // tf32-rounded x
__device__ float g_hc[MROWS * DIM];          // tf32-rounded h[1..T]
__device__ float g_wc[4 * DIM * DIM];        // tf32-rounded [W_x, W_alpha, W_delta, W_out]

// ---------------- helpers ----------------
__device__ __forceinline__ uint32_t f2tf32(float x) {
    uint32_t r;
    asm("cvt.rna.tf32.f32 %0, %1;" : "=r"(r) : "f"(x));
    return r;
}

__device__ __forceinline__ void mma_tf32(float* c, const uint32_t* a, const uint32_t* b) {
    asm volatile(
        "mma.sync.aligned.m16n8k8.row.col.f32.tf32.tf32.f32 "
        "{%0,%1,%2,%3}, {%4,%5,%6,%7}, {%8,%9}, {%0,%1,%2,%3};"
        : "+f"(c[0]), "+f"(c[1]), "+f"(c[2]), "+f"(c[3])
        : "r"(a[0]), "r"(a[1]), "r"(a[2]), "r"(a[3]), "r"(b[0]), "r"(b[1]));
}

__device__ __forceinline__ void ldsm_x4(uint32_t& r0, uint32_t& r1, uint32_t& r2, uint32_t& r3,
                                        uint32_t addr) {
    asm volatile("ldmatrix.sync.aligned.m8n8.x4.shared.b16 {%0,%1,%2,%3}, [%4];"
                 : "=r"(r0), "=r"(r1), "=r"(r2), "=r"(r3) : "r"(addr));
}

__device__ __forceinline__ uint32_t smem_u32(const void* p) {
    uint32_t a;
    asm("{ .reg .u64 t; cvta.to.shared.u64 t, %1; cvt.u32.u64 %0, t; }" : "=r"(a) : "l"(p));
    return a;
}

__device__ __forceinline__ void cp16(uint32_t saddr, const float* gptr) {
    size_t ga = __cvta_generic_to_global(gptr);
    asm volatile("cp.async.cg.shared.global [%0], [%1], 16;" :: "r"(saddr), "l"(ga));
}

// ---------------- tf32 pre-round (elementwise) ----------------
__global__ void __launch_bounds__(256)
tf32_convert_kernel(const float* __restrict__ in, float* __restrict__ out, int n4)
{
    int i = blockIdx.x * blockDim.x + threadIdx.x;
    if (i < n4) {
        float4 v = ((const float4*)in)[i];
        uint4 o;
        o.x = f2tf32(v.x); o.y = f2tf32(v.y); o.z = f2tf32(v.z); o.w = f2tf32(v.w);
        ((uint4*)out)[i] = o;
    }
}

// ---------------- GEMM: C[M,N] = A[M,K] @ W[N,K]^T ----------------
// 256 threads, warp grid 2x4, warp tile 64x32, block 128x128.
// BK=32, cp.async 3-stage pipeline, ONE barrier per 32-K (32 iters, 4 k8-chunks each).
// ~115 regs + 110.6KB smem -> 2 CTAs/SM = 16 warps/SM.
// fused=1: blockIdx.x in [0,24): wsel = x>>3 selects (W slot, bias, C, mode 0/1/2)
//   mode 0: y = acc + bias;  1: y = 1+softplus(acc+bias);  2: y = sigmoid(acc+bias)
// fused=0: mode 3: y = compete * silu(acc)
#define BM 128
#define BN 128
#define BK 32
#define LDW 36                        // smem row stride in words (144B)
#define ROWSZ (LDW * 4)               // 144 bytes
#define STAGE_A (BM * ROWSZ)          // 18432
#define STAGE_BYTES (2 * STAGE_A)     // 36864 (A then B)
#define NPIPE 3
#define SMEM_GEMM (NPIPE * STAGE_BYTES)   // 110592

__global__ void __launch_bounds__(256, 2)
gemm_tf32_kernel(const float* __restrict__ A,
                 const float* __restrict__ Wc,
                 const float* __restrict__ bias0, const float* __restrict__ bias1,
                 const float* __restrict__ bias2,
                 const float* __restrict__ comp,
                 float* __restrict__ C0, float* __restrict__ C1, float* __restrict__ C2,
                 int fused)
{
    extern __shared__ char smem[];
    const int K = DIM, N = DIM;

    int mode, ntile;
    const float* W;
    const float* bias;
    float* C;
    if (fused) {
        int wsel = blockIdx.x >> 3;
        ntile = blockIdx.x & 7;
        mode = wsel;
        W    = Wc + (size_t)wsel * DIM * DIM;
        bias = (wsel == 0) ? bias0 : ((wsel == 1) ? bias1 : bias2);
        C    = (wsel == 0) ? C0 : ((wsel == 1) ? C1 : C2);
    } else {
        mode = 3; ntile = blockIdx.x; W = Wc; bias = bias0; C = C0;
    }

    const int tid  = threadIdx.x;           // 0..255
    const int lane = tid & 31;
    const int warp = tid >> 5;              // 0..7
    const int warpM = warp >> 2;            // 0..1
    const int warpN = warp & 3;             // 0..3
    const int wmBase = warpM * 64;
    const int wnBase = warpN * 32;

    const int m0 = blockIdx.y * BM;
    const int n0 = ntile * BN;

    // staging: 2 threads per row, each covers 64B (16 floats) = 4 cp16 per matrix
    const int sRow = tid >> 1;              // 0..127
    const int sCo  = (tid & 1) * 16;        // 0 or 16 floats
    const float* Aptr = A + (size_t)(m0 + sRow) * K + sCo;
    const float* Wptr = W + (size_t)(n0 + sRow) * K + sCo;

    const uint32_t sb = smem_u32(smem);
    const uint32_t sRowA = sb + (uint32_t)sRow * ROWSZ + (uint32_t)sCo * 4;
    const uint32_t sRowB = sRowA + STAGE_A;

    // ldmatrix per-thread source row/col within a 16x8 tf32 tile
    const int lRow = (lane & 7) + ((lane >> 3) & 1) * 8;  // 0..15
    const int lK   = (lane >> 4) * 4;                     // 0 or 4
    const uint32_t aBase = sb + (uint32_t)(wmBase + lRow) * ROWSZ + (uint32_t)lK * 4;
    const uint32_t bBase = sb + STAGE_A + (uint32_t)(wnBase + lRow) * ROWSZ + (uint32_t)lK * 4;

    float acc[4][4][4];
#pragma unroll
    for (int i = 0; i < 4; i++)
#pragma unroll
        for (int j = 0; j < 4; j++)
#pragma unroll
            for (int r = 0; r < 4; r++) acc[i][j][r] = 0.f;

    const int grp = lane >> 2;   // 0..7
    const int tig = lane & 3;    // 0..3

    const int NKT = K / BK;      // 32

    // ---- prologue: issue stages 0,1 ----
#pragma unroll
    for (int s = 0; s < NPIPE - 1; s++) {
        const uint32_t so = (uint32_t)s * STAGE_BYTES;
        const int k = s * BK;
#pragma unroll
        for (int p = 0; p < 4; p++) {
            cp16(sRowA + so + 16 * p, Aptr + k + 4 * p);
            cp16(sRowB + so + 16 * p, Wptr + k + 4 * p);
        }
        asm volatile("cp.async.commit_group;");
    }

    int bufC = 0;                 // compute-stage buffer index (kt mod 3)
#pragma unroll 1
    for (int kt = 0; kt < NKT; kt++) {
        asm volatile("cp.async.wait_group 1;");   // stage kt landed (kt+1 in flight)
        __syncthreads();                           // all threads' copies visible; reads of kt-1 done

        // issue stage kt+2 into buffer (kt+2)%3 == buffer of kt-1
        if (kt + 2 < NKT) {
            int bufI = bufC + 2; if (bufI >= NPIPE) bufI -= NPIPE;
            const uint32_t so = (uint32_t)bufI * STAGE_BYTES;
            const int k = (kt + 2) * BK;
#pragma unroll
            for (int p = 0; p < 4; p++) {
                cp16(sRowA + so + 16 * p, Aptr + k + 4 * p);
                cp16(sRowB + so + 16 * p, Wptr + k + 4 * p);
            }
        }
        asm volatile("cp.async.commit_group;");

        // ---- compute on stage bufC: 4 k8-chunks, 24 LDSM + 64 MMA per warp ----
        const uint32_t so = (uint32_t)bufC * STAGE_BYTES;
        const uint32_t aB = aBase + so;
        const uint32_t bB = bBase + so;
#pragma unroll
        for (int kk = 0; kk < BK; kk += 8) {
            const uint32_t kOff = (uint32_t)kk * 4;
            uint32_t af[4][4];
#pragma unroll
            for (int mt = 0; mt < 4; mt++)
                ldsm_x4(af[mt][0], af[mt][1], af[mt][2], af[mt][3],
                        aB + (uint32_t)(mt * 16) * ROWSZ + kOff);
            uint32_t bf[4][2];
#pragma unroll
            for (int pr = 0; pr < 2; pr++)
                ldsm_x4(bf[2 * pr][0], bf[2 * pr + 1][0], bf[2 * pr][1], bf[2 * pr + 1][1],
                        bB + (uint32_t)(pr * 16) * ROWSZ + kOff);
#pragma unroll
            for (int mt = 0; mt < 4; mt++)
#pragma unroll
                for (int nt = 0; nt < 4; nt++)
                    mma_tf32(acc[mt][nt], af[mt], bf[nt]);
        }

        bufC++; if (bufC >= NPIPE) bufC -= NPIPE;
    }

    // ---- epilogue (float2 stores: reg pairs are adjacent columns) ----
#pragma unroll
    for (int mt = 0; mt < 4; mt++) {
#pragma unroll
        for (int nt = 0; nt < 4; nt++) {
#pragma unroll
            for (int half = 0; half < 2; half++) {
                int row = m0 + wmBase + mt * 16 + grp + half * 8;
                int col = n0 + wnBase + nt * 8 + 2 * tig;
                float v0 = acc[mt][nt][half * 2 + 0];
                float v1 = acc[mt][nt][half * 2 + 1];
                float y0, y1;
                if (mode == 0) {
                    y0 = v0 + bias[col]; y1 = v1 + bias[col + 1];
                } else if (mode == 1) {
                    float x0 = v0 + bias[col], x1 = v1 + bias[col + 1];
                    y0 = 1.0f + ((x0 > 20.f) ? x0 : log1pf(__expf(x0)));
                    y1 = 1.0f + ((x1 > 20.f) ? x1 : log1pf(__expf(x1)));
                } else if (mode == 2) {
                    float x0 = v0 + bias[col], x1 = v1 + bias[col + 1];
                    y0 = 1.0f / (1.0f + __expf(-x0));
                    y1 = 1.0f / (1.0f + __expf(-x1));
                } else {
                    float s0 = v0 / (1.0f + __expf(-v0));
                    float s1 = v1 / (1.0f + __expf(-v1));
                    const float2 cc = *(const float2*)(comp + (size_t)row * N + col);
                    y0 = cc.x * s0; y1 = cc.y * s1;
                }
                float2 o; o.x = y0; o.y = y1;
                *(float2*)(C + (size_t)row * N + col) = o;
            }
        }
    }
}

// ---------------- sequential scan: 16-deep batched prefetch ----------------
__global__ void __launch_bounds__(128)
scan_kernel(const float* __restrict__ vx, const float* __restrict__ alpha,
            const float* __restrict__ delta, const float* __restrict__ h0,
            const float* __restrict__ r_h, float* __restrict__ out_h,
            float* __restrict__ hc)
{
    int gtid = blockIdx.x * 128 + threadIdx.x;   // 0..16383
    int b = gtid >> 10;
    int d = gtid & 1023;
    size_t base = (size_t)b * DIM + d;

    float rh = r_h[d];
    float h = h0[base];
    out_h[base] = h;

    float cv[16], ca[16], cd[16], nv[16], na[16], nd[16];
#pragma unroll
    for (int i = 0; i < 16; i++) {
        size_t o = (size_t)i * BD + base;
        cv[i] = __ldcs(vx + o); ca[i] = __ldcs(alpha + o); cd[i] = __ldcs(delta + o);
    }

    for (int t0 = 0; t0 < TT; t0 += 16) {
        const bool more = (t0 + 16) < TT;
        if (more) {
#pragma unroll
            for (int i = 0; i < 16; i++) {
                size_t o = (size_t)(t0 + 16 + i) * BD + base;
                nv[i] = __ldcs(vx + o); na[i] = __ldcs(alpha + o); nd[i] = __ldcs(delta + o);
            }
        }
#pragma unroll
        for (int i = 0; i < 16; i++) {
            float v = cv[i] + rh * h;
            float av = fminf(fmaxf(fabsf(v), 1e-6f), 10.0f);
            float cand = __powf(av, ca[i]);
            cand = (v >= 0.f) ? cand : -cand;
            if (v == 0.f) cand = 0.f;
            h = h + cd[i] * (cand - h);
            size_t o = (size_t)(t0 + i) * BD + base;
            __stcs(out_h + o + BD, h);
            __stcs(hc + o, __uint_as_float(f2tf32(h)));
        }
        if (more) {
#pragma unroll
            for (int i = 0; i < 16; i++) { cv[i] = nv[i]; ca[i] = na[i]; cd[i] = nd[i]; }
        }
    }
}

// ---------------- compete = group softmax over h[1:], fully parallel ----------------
__global__ void __launch_bounds__(256)
compete_kernel(const float* __restrict__ h, float* __restrict__ comp)
{
    size_t idx = (size_t)blockIdx.x * blockDim.x + threadIdx.x;
    float v = h[idx];
    float m = v;
#pragma unroll
    for (int o = 16; o > 0; o >>= 1) m = fmaxf(m, __shfl_xor_sync(0xffffffffu, m, o));
    float e = __expf(v - m);
    float s = e;
#pragma unroll
    for (int o = 16; o > 0; o >>= 1) s += __shfl_xor_sync(0xffffffffu, s, o);
    comp[idx] = e / s;
}

// ---------------- launch ----------------
extern "C" void kernel_launch(void* const* d_in, const int* in_sizes, int n_in,
                              void* d_out, int out_size)
{
    const float* x       = (const float*)d_in[0];
    const float* h0      = (const float*)d_in[1];
    const float* W_x     = (const float*)d_in[2];
    const float* r_h     = (const float*)d_in[3];
    const float* b       = (const float*)d_in[4];
    const float* W_alpha = (const float*)d_in[5];
    const float* b_alpha = (const float*)d_in[6];
    const float* W_delta = (const float*)d_in[7];
    const float* b_delta = (const float*)d_in[8];
    const float* W_out   = (const float*)d_in[9];

    float* out = (float*)d_out;
    float* out_h = out;                                  // [T+1,B,D]
    float* out_y = out + (size_t)(TT + 1) * BD;          // [T,B,D]

    float *vx, *al, *dl, *cp, *xc, *hc, *wc;
    cudaGetSymbolAddress((void**)&vx, g_vx);
    cudaGetSymbolAddress((void**)&al, g_alpha);
    cudaGetSymbolAddress((void**)&dl, g_delta);
    cudaGetSymbolAddress((void**)&cp, g_compete);
    cudaGetSymbolAddress((void**)&xc, g_xc);
    cudaGetSymbolAddress((void**)&hc, g_hc);
    cudaGetSymbolAddress((void**)&wc, g_wc);

    cudaFuncSetAttribute(gemm_tf32_kernel, cudaFuncAttributeMaxDynamicSharedMemorySize,
                         SMEM_GEMM);

    // 0) pre-round inputs to tf32 bit patterns
    const int WN4 = DIM * DIM / 4;                       // 262144
    tf32_convert_kernel<<<(MROWS * DIM / 4 + 255) / 256, 256>>>(x, xc, MROWS * DIM / 4);
    tf32_convert_kernel<<<(WN4 + 255) / 256, 256>>>(W_x,     wc + 0 * DIM * DIM, WN4);
    tf32_convert_kernel<<<(WN4 + 255) / 256, 256>>>(W_alpha, wc + 1 * DIM * DIM, WN4);
    tf32_convert_kernel<<<(WN4 + 255) / 256, 256>>>(W_delta, wc + 2 * DIM * DIM, WN4);
    tf32_convert_kernel<<<(WN4 + 255) / 256, 256>>>(W_out,   wc + 3 * DIM * DIM, WN4);

    // 1) fused projections
    dim3 pgrid(3 * (DIM / BN), MROWS / BM);   // (24, 128)
    gemm_tf32_kernel<<<pgrid, 256, SMEM_GEMM>>>(xc, wc, b, b_alpha, b_delta,
                                                nullptr, vx, al, dl, 1);
    // 2) sequential scan -> exact h (into d_out) + tf32-rounded h (scratch)
    scan_kernel<<<128, 128>>>(vx, al, dl, h0, r_h, out_h, hc);
    // 3) group softmax over h[1:]
    compete_kernel<<<(MROWS * DIM) / 256, 256>>>(out_h + BD, cp);
    // 4) output GEMM with compete*silu epilogue
    dim3 ogrid(DIM / BN, MROWS / BM);          // (8, 128)
    gemm_tf32_kernel<<<ogrid, 256, SMEM_GEMM>>>(hc, wc + 3 * (size_t)DIM * DIM,
                                                nullptr, nullptr, nullptr,
                                                cp, out_y, nullptr, nullptr, 0);
}

// round 10
// speedup vs baseline: 1.1983x; 1.1983x over previous
#include <cuda_runtime.h>
#include <cuda_bf16.h>
#include <cstdint>

#define DIM 1024
#define NGROUPS 32
#define GSIZE 32
#define TT 1024
#define BB 16
#define MROWS (TT * BB)          // 16384
#define BD (BB * DIM)            // 16384

// ---------------- scratch (device globals; no allocation allowed) ----------------
__device__ float g_vx[MROWS * DIM];
__device__ float g_alpha[MROWS * DIM];
__device__ float g_delta[MROWS * DIM];
__device__ float g_compete[MROWS * DIM];

// ---------------- helpers ----------------
__device__ __forceinline__ uint32_t f2tf32(float x) {
    uint32_t r;
    asm("cvt.rna.tf32.f32 %0, %1;" : "=r"(r) : "f"(x));
    return r;
}

__device__ __forceinline__ void mma_tf32(float* c, const uint32_t* a, const uint32_t* b) {
    asm volatile(
        "mma.sync.aligned.m16n8k8.row.col.f32.tf32.tf32.f32 "
        "{%0,%1,%2,%3}, {%4,%5,%6,%7}, {%8,%9}, {%0,%1,%2,%3};"
        : "+f"(c[0]), "+f"(c[1]), "+f"(c[2]), "+f"(c[3])
        : "r"(a[0]), "r"(a[1]), "r"(a[2]), "r"(a[3]), "r"(b[0]), "r"(b[1]));
}

__device__ __forceinline__ void ldsm_x4(uint32_t& r0, uint32_t& r1, uint32_t& r2, uint32_t& r3,
                                        uint32_t addr) {
    asm volatile("ldmatrix.sync.aligned.m8n8.x4.shared.b16 {%0,%1,%2,%3}, [%4];"
                 : "=r"(r0), "=r"(r1), "=r"(r2), "=r"(r3) : "r"(addr));
}

__device__ __forceinline__ uint32_t smem_u32(const void* p) {
    uint32_t a;
    asm("{ .reg .u64 t; cvta.to.shared.u64 t, %1; cvt.u32.u64 %0, t; }" : "=r"(a) : "l"(p));
    return a;
}

// ---------------- GEMM: C[M,N] = A[M,K] @ W[N,K]^T (R3 config, proven) ----------
// Block 128x128, 8 warps 2x4, warp tile 64x32, register double-buffer + ldmatrix.
// fused=1: blockIdx.x in [0,24): wsel = x>>3 selects (W,bias,C,mode 0/1/2)
//   mode 0: y = acc + bias;  1: y = 1+softplus(acc+bias);  2: y = sigmoid(acc+bias)
// fused=0: mode 3: y = compete * silu(acc)
#define BM 128
#define BN 128
#define BK 16
#define LDW 20    // smem row stride in words (80B): conflict-free for LDSM & STS

__global__ void __launch_bounds__(256, 2)
gemm_tf32_kernel(const float* __restrict__ A,
                 const float* __restrict__ W0, const float* __restrict__ W1,
                 const float* __restrict__ W2,
                 const float* __restrict__ bias0, const float* __restrict__ bias1,
                 const float* __restrict__ bias2,
                 const float* __restrict__ comp,
                 float* __restrict__ C0, float* __restrict__ C1, float* __restrict__ C2,
                 int fused)
{
    __shared__ uint32_t As[2][BM][LDW];
    __shared__ uint32_t Bs[2][BN][LDW];

    const int K = DIM, N = DIM;

    int mode, ntile;
    const float* W;
    const float* bias;
    float* C;
    if (fused) {
        int wsel = blockIdx.x >> 3;
        ntile = blockIdx.x & 7;
        mode = wsel;
        W    = (wsel == 0) ? W0 : ((wsel == 1) ? W1 : W2);
        bias = (wsel == 0) ? bias0 : ((wsel == 1) ? bias1 : bias2);
        C    = (wsel == 0) ? C0 : ((wsel == 1) ? C1 : C2);
    } else {
        mode = 3; ntile = blockIdx.x; W = W0; bias = bias0; C = C0;
    }

    const int tid  = threadIdx.x;
    const int lane = tid & 31;
    const int warp = tid >> 5;
    const int warpM = warp >> 2;   // 0..1
    const int warpN = warp & 3;    // 0..3
    const int wmBase = warpM * 64;
    const int wnBase = warpN * 32;

    const int m0 = blockIdx.y * BM;
    const int n0 = ntile * BN;

    const int ldRow = tid >> 2;
    const int ldCol = (tid & 3) * 4;

    const float* Aptr  = A + (size_t)(m0 + ldRow) * K + ldCol;
    const float* Aptr2 = Aptr + (size_t)64 * K;
    const float* Wptr  = W + (size_t)(n0 + ldRow) * K + ldCol;
    const float* Wptr2 = Wptr + (size_t)64 * K;

    // ldmatrix per-thread source row/col within a 16x8 tf32 tile
    const int lRow = (lane & 7) + ((lane >> 3) & 1) * 8;  // 0..15
    const int lK   = (lane >> 4) * 4;                     // 0 or 4

    const uint32_t AsBase = smem_u32(&As[0][0][0]);
    const uint32_t BsBase = smem_u32(&Bs[0][0][0]);

    float acc[4][4][4];
#pragma unroll
    for (int i = 0; i < 4; i++)
#pragma unroll
        for (int j = 0; j < 4; j++)
#pragma unroll
            for (int r = 0; r < 4; r++) acc[i][j][r] = 0.f;

    const int grp = lane >> 2;   // 0..7
    const int tig = lane & 3;    // 0..3

    // ---- prologue: stage k0=0 into buffer 0 ----
    float4 ra0 = *(const float4*)(Aptr);
    float4 ra1 = *(const float4*)(Aptr2);
    float4 rb0 = *(const float4*)(Wptr);
    float4 rb1 = *(const float4*)(Wptr2);
    {
        uint4 v;
        v.x = f2tf32(ra0.x); v.y = f2tf32(ra0.y); v.z = f2tf32(ra0.z); v.w = f2tf32(ra0.w);
        *(uint4*)&As[0][ldRow][ldCol] = v;
        v.x = f2tf32(ra1.x); v.y = f2tf32(ra1.y); v.z = f2tf32(ra1.z); v.w = f2tf32(ra1.w);
        *(uint4*)&As[0][ldRow + 64][ldCol] = v;
        v.x = f2tf32(rb0.x); v.y = f2tf32(rb0.y); v.z = f2tf32(rb0.z); v.w = f2tf32(rb0.w);
        *(uint4*)&Bs[0][ldRow][ldCol] = v;
        v.x = f2tf32(rb1.x); v.y = f2tf32(rb1.y); v.z = f2tf32(rb1.z); v.w = f2tf32(rb1.w);
        *(uint4*)&Bs[0][ldRow + 64][ldCol] = v;
    }
    __syncthreads();

    int cur = 0;
    for (int k0 = 0; k0 < K; k0 += BK) {
        const bool has_next = (k0 + BK) < K;
        if (has_next) {
            int kn = k0 + BK;
            ra0 = *(const float4*)(Aptr  + kn);
            ra1 = *(const float4*)(Aptr2 + kn);
            rb0 = *(const float4*)(Wptr  + kn);
            rb1 = *(const float4*)(Wptr2 + kn);
        }

        // ---- compute on buffer `cur` via ldmatrix ----
        const uint32_t aRow = (uint32_t)(cur * BM + wmBase + lRow) * (LDW * 4);
        const uint32_t bRow = (uint32_t)(cur * BN + wnBase + lRow) * (LDW * 4);
#pragma unroll
        for (int kk = 0; kk < BK; kk += 8) {
            const uint32_t kOff = (uint32_t)(kk + lK) * 4;
            uint32_t af[4][4];
#pragma unroll
            for (int mt = 0; mt < 4; mt++) {
                uint32_t addr = AsBase + aRow + (uint32_t)(mt * 16) * (LDW * 4) + kOff;
                ldsm_x4(af[mt][0], af[mt][1], af[mt][2], af[mt][3], addr);
            }
            uint32_t bf[4][2];
#pragma unroll
            for (int pr = 0; pr < 2; pr++) {
                uint32_t addr = BsBase + bRow + (uint32_t)(pr * 16) * (LDW * 4) + kOff;
                ldsm_x4(bf[2 * pr][0], bf[2 * pr + 1][0], bf[2 * pr][1], bf[2 * pr + 1][1], addr);
            }
#pragma unroll
            for (int mt = 0; mt < 4; mt++)
#pragma unroll
                for (int nt = 0; nt < 4; nt++)
                    mma_tf32(acc[mt][nt], af[mt], bf[nt]);
        }

        if (has_next) {
            int nxt = cur ^ 1;
            uint4 v;
            v.x = f2tf32(ra0.x); v.y = f2tf32(ra0.y); v.z = f2tf32(ra0.z); v.w = f2tf32(ra0.w);
            *(uint4*)&As[nxt][ldRow][ldCol] = v;
            v.x = f2tf32(ra1.x); v.y = f2tf32(ra1.y); v.z = f2tf32(ra1.z); v.w = f2tf32(ra1.w);
            *(uint4*)&As[nxt][ldRow + 64][ldCol] = v;
            v.x = f2tf32(rb0.x); v.y = f2tf32(rb0.y); v.z = f2tf32(rb0.z); v.w = f2tf32(rb0.w);
            *(uint4*)&Bs[nxt][ldRow][ldCol] = v;
            v.x = f2tf32(rb1.x); v.y = f2tf32(rb1.y); v.z = f2tf32(rb1.z); v.w = f2tf32(rb1.w);
            *(uint4*)&Bs[nxt][ldRow + 64][ldCol] = v;
        }
        __syncthreads();
        cur ^= 1;
    }

    // ---- epilogue (float2 stores: reg pairs are adjacent columns) ----
#pragma unroll
    for (int mt = 0; mt < 4; mt++) {
#pragma unroll
        for (int nt = 0; nt < 4; nt++) {
#pragma unroll
            for (int half = 0; half < 2; half++) {
                int row = m0 + wmBase + mt * 16 + grp + half * 8;
                int col = n0 + wnBase + nt * 8 + 2 * tig;
                float v0 = acc[mt][nt][half * 2 + 0];
                float v1 = acc[mt][nt][half * 2 + 1];
                float y0, y1;
                if (mode == 0) {
                    y0 = v0 + bias[col]; y1 = v1 + bias[col + 1];
                } else if (mode == 1) {
                    float x0 = v0 + bias[col], x1 = v1 + bias[col + 1];
                    y0 = 1.0f + ((x0 > 20.f) ? x0 : log1pf(__expf(x0)));
                    y1 = 1.0f + ((x1 > 20.f) ? x1 : log1pf(__expf(x1)));
                } else if (mode == 2) {
                    float x0 = v0 + bias[col], x1 = v1 + bias[col + 1];
                    y0 = 1.0f / (1.0f + __expf(-x0));
                    y1 = 1.0f / (1.0f + __expf(-x1));
                } else {
                    float s0 = v0 / (1.0f + __expf(-v0));
                    float s1 = v1 / (1.0f + __expf(-v1));
                    const float2 cc = *(const float2*)(comp + (size_t)row * N + col);
                    y0 = cc.x * s0; y1 = cc.y * s1;
                }
                float2 o; o.x = y0; o.y = y1;
                *(float2*)(C + (size_t)row * N + col) = o;
            }
        }
    }
}

// ---------------- sequential scan: 16-deep batch prefetch, 256 blocks x 64 thr ----
__global__ void __launch_bounds__(64)
scan_kernel(const float* __restrict__ vx, const float* __restrict__ alpha,
            const float* __restrict__ delta, const float* __restrict__ h0,
            const float* __restrict__ r_h, float* __restrict__ out_h)
{
    int gtid = blockIdx.x * 64 + threadIdx.x;   // 0..16383
    int b = gtid >> 10;
    int d = gtid & 1023;
    size_t base = (size_t)b * DIM + d;

    float rh = r_h[d];
    float h = h0[base];
    out_h[base] = h;

    float cv[16], ca[16], cd[16], nv[16], na[16], nd[16];
#pragma unroll
    for (int i = 0; i < 16; i++) {
        size_t o = (size_t)i * BD + base;
        cv[i] = __ldcs(vx + o); ca[i] = __ldcs(alpha + o); cd[i] = __ldcs(delta + o);
    }

    for (int t0 = 0; t0 < TT; t0 += 16) {
        const bool more = (t0 + 16) < TT;
        if (more) {
            // issue the entire next batch BEFORE the dependency chain
#pragma unroll
            for (int i = 0; i < 16; i++) {
                size_t o = (size_t)(t0 + 16 + i) * BD + base;
                nv[i] = __ldcs(vx + o); na[i] = __ldcs(alpha + o); nd[i] = __ldcs(delta + o);
            }
        }
#pragma unroll
        for (int i = 0; i < 16; i++) {
            float v = cv[i] + rh * h;
            float av = fminf(fmaxf(fabsf(v), 1e-6f), 10.0f);
            float cand = __powf(av, ca[i]);
            cand = (v >= 0.f) ? cand : -cand;
            if (v == 0.f) cand = 0.f;     // jnp.sign(0) == 0
            h = h + cd[i] * (cand - h);
            __stcs(out_h + (size_t)(t0 + i + 1) * BD + base, h);
        }
        if (more) {
#pragma unroll
            for (int i = 0; i < 16; i++) { cv[i] = nv[i]; ca[i] = na[i]; cd[i] = nd[i]; }
        }
    }
}

// ---------------- compete = group softmax over h[1:], fully parallel ----------------
__global__ void __launch_bounds__(256)
compete_kernel(const float* __restrict__ h, float* __restrict__ comp)
{
    size_t idx = (size_t)blockIdx.x * blockDim.x + threadIdx.x;
    float v = h[idx];
    float m = v;
#pragma unroll
    for (int o = 16; o > 0; o >>= 1) m = fmaxf(m, __shfl_xor_sync(0xffffffffu, m, o));
    float e = __expf(v - m);
    float s = e;
#pragma unroll
    for (int o = 16; o > 0; o >>= 1) s += __shfl_xor_sync(0xffffffffu, s, o);
    comp[idx] = e / s;
}

// ---------------- launch ----------------
extern "C" void kernel_launch(void* const* d_in, const int* in_sizes, int n_in,
                              void* d_out, int out_size)
{
    const float* x       = (const float*)d_in[0];   // [T,B,D]
    const float* h0      = (const float*)d_in[1];   // [B,D]
    const float* W_x     = (const float*)d_in[2];   // [D,D]
    const float* r_h     = (const float*)d_in[3];   // [D]
    const float* b       = (const float*)d_in[4];   // [D]
    const float* W_alpha = (const float*)d_in[5];
    const float* b_alpha = (const float*)d_in[6];
    const float* W_delta = (const float*)d_in[7];
    const float* b_delta = (const float*)d_in[8];
    const float* W_out   = (const float*)d_in[9];

    float* out = (float*)d_out;
    float* out_h = out;                                  // [T+1,B,D]
    float* out_y = out + (size_t)(TT + 1) * BD;          // [T,B,D]

    float *vx, *al, *dl, *cp;
    cudaGetSymbolAddress((void**)&vx, g_vx);
    cudaGetSymbolAddress((void**)&al, g_alpha);
    cudaGetSymbolAddress((void**)&dl, g_delta);
    cudaGetSymbolAddress((void**)&cp, g_compete);

    // 1) fused projections: one launch, 3 weights (A tile L2-shared across weights)
    dim3 pgrid(3 * (DIM / BN), MROWS / BM);   // (24, 128)
    gemm_tf32_kernel<<<pgrid, 256>>>(x, W_x, W_alpha, W_delta, b, b_alpha, b_delta,
                                     nullptr, vx, al, dl, 1);
    // 2) sequential scan -> h states (written straight into d_out)
    scan_kernel<<<256, 64>>>(vx, al, dl, h0, r_h, out_h);
    // 3) group softmax over h[1:]
    compete_kernel<<<(MROWS * DIM) / 256, 256>>>(out_h + BD, cp);
    // 4) output GEMM with compete*silu epilogue
    dim3 ogrid(DIM / BN, MROWS / BM);          // (8, 128)
    gemm_tf32_kernel<<<ogrid, 256>>>(out_h + BD, W_out, nullptr, nullptr,
                                     nullptr, nullptr, nullptr,
                                     cp, out_y, nullptr, nullptr, 0);
}